// round 12
// baseline (speedup 1.0000x reference)
#include <cuda_runtime.h>

#define Bc   2
#define Mq   16384
#define Np   4096
#define Cin  128
#define CsF  256
#define DoC  128
#define NCOLS (Bc*Mq)        // 32768
#define NBLK  256            // gemm1/gemm2 grid
#define PH   2048            // points per half (knn split)

// ---------------- scratch (device globals; no runtime allocation) -------------
__device__ __align__(16) float d_W1t[384*DoC];
__device__ __align__(16) float d_W2t[DoC*DoC];
__device__ __align__(16) float d_P  [Bc*Np*DoC];
__device__ float d_cd[Bc*Mq*6];
__device__ int   d_ci[Bc*Mq*6];
__device__ __align__(16) float d_z1 [Bc*DoC*Mq];
__device__ __align__(16) float d_z2 [Bc*DoC*Mq];
__device__ __align__(16) float d_psum[DoC*NBLK];   // channel-major [ch][blk]
__device__ __align__(16) float d_psq [DoC*NBLK];
__device__ float d_bn1[2*DoC];

// ---------------- cp.async helpers ----------------
__device__ __forceinline__ void cp16(float* s, const float* g) {
  unsigned sa = (unsigned)__cvta_generic_to_shared(s);
  asm volatile("cp.async.cg.shared.global [%0], [%1], 16;\n" :: "r"(sa), "l"(g));
}
__device__ __forceinline__ void cp_commit() { asm volatile("cp.async.commit_group;\n"); }
template<int N> __device__ __forceinline__ void cp_wait() {
  asm volatile("cp.async.wait_group %0;\n" :: "n"(N));
}

// ---------------- W transpose ----------------
__global__ __launch_bounds__(256) void transpose_w_kernel(
    const float* __restrict__ W1, const float* __restrict__ W2) {
  int e = blockIdx.x * 256 + threadIdx.x;
  if (e < 384*DoC) {
    int k = e >> 7, o = e & 127;
    d_W1t[e] = W1[o*384 + k];
  } else {
    int e2 = e - 384*DoC;
    int k = e2 >> 7, o = e2 & 127;
    d_W2t[e2] = W2[o*DoC + k];
  }
}

// ---------------- fused: knn 2q/thread (blocks 0..127) + gemmP (blocks 128..255) ----------------
__global__ __launch_bounds__(256) void knn_gemmP_kernel(
    const float* __restrict__ xyz, const float* __restrict__ sub_xyz,
    const float* __restrict__ sub_x) {
  extern __shared__ float smem[];
  int bx = blockIdx.x;
  int tid = threadIdx.x;

  if (bx < 128) {
    // ---------------- knn role: 2 queries per thread ----------------
    float4* pts = (float4*)smem;   // 32KB
    int b    = bx >> 6;
    int half = (bx >> 5) & 1;
    int m0   = ((bx & 31) << 9) + tid;   // queries m0 and m0+256
    const float* sp = sub_xyz + (size_t)b * 3 * Np + half * PH;
    for (int i = tid; i < PH; i += 256) {
      float px = sp[i], py = sp[Np + i], pz = sp[2*Np + i];
      pts[i] = make_float4(px, py, pz, fmaf(px, px, fmaf(py, py, pz*pz)));
    }
    __syncthreads();
    const float* qp = xyz + (size_t)b * 3 * Mq;
    int mA = m0, mB = m0 + 256;
    float nxA = -2.f*qp[mA], nyA = -2.f*qp[Mq+mA], nzA = -2.f*qp[2*Mq+mA];
    float nxB = -2.f*qp[mB], nyB = -2.f*qp[Mq+mB], nzB = -2.f*qp[2*Mq+mB];

    float a0=3.4e38f,a1=3.4e38f,a2=3.4e38f; int ja0=0,ja1=0,ja2=0;
    float b0=3.4e38f,b1=3.4e38f,b2=3.4e38f; int jb0=0,jb1=0,jb2=0;
    #pragma unroll 4
    for (int i = 0; i < PH; i++) {
      float4 p = pts[i];
      float eA = fmaf(nxA, p.x, fmaf(nyA, p.y, fmaf(nzA, p.z, p.w)));
      float eB = fmaf(nxB, p.x, fmaf(nyB, p.y, fmaf(nzB, p.z, p.w)));
      if (eA < a2) {
        if (eA < a1) {
          a2 = a1; ja2 = ja1;
          if (eA < a0) { a1 = a0; ja1 = ja0; a0 = eA; ja0 = i; }
          else         { a1 = eA; ja1 = i; }
        } else { a2 = eA; ja2 = i; }
      }
      if (eB < b2) {
        if (eB < b1) {
          b2 = b1; jb2 = jb1;
          if (eB < b0) { b1 = b0; jb1 = jb0; b0 = eB; jb0 = i; }
          else         { b1 = eB; jb1 = i; }
        } else { b2 = eB; jb2 = i; }
      }
    }
    int off = half * PH;
    size_t baseA = ((size_t)(b * Mq + mA) * 2 + half) * 3;
    d_cd[baseA+0]=a0; d_cd[baseA+1]=a1; d_cd[baseA+2]=a2;
    d_ci[baseA+0]=ja0+off; d_ci[baseA+1]=ja1+off; d_ci[baseA+2]=ja2+off;
    size_t baseB = ((size_t)(b * Mq + mB) * 2 + half) * 3;
    d_cd[baseB+0]=b0; d_cd[baseB+1]=b1; d_cd[baseB+2]=b2;
    d_ci[baseB+0]=jb0+off; d_ci[baseB+1]=jb1+off; d_ci[baseB+2]=jb2+off;
    return;
  }

  // ---------------- gemmP role ----------------
  int bxp = bx - 128;                 // 0..127
  float* Ws = smem;                   // [2][32][128]
  float* Xs = smem + 8192;            // [2][32][64]
  int b  = bxp >> 6;
  int n0 = (bxp & 63) << 6;
  int tx = tid & 15, ty = tid >> 4;
  const float* xb = sub_x + (size_t)b * CsF * Np;
  float acc[8][4];
  #pragma unroll
  for (int i = 0; i < 8; i++)
    #pragma unroll
    for (int j = 0; j < 4; j++) acc[i][j] = 0.0f;

  auto load_chunk = [&](int kc, int s) {
    float* Wd = Ws + s * 4096;
    float* Xd = Xs + s * 2048;
    #pragma unroll
    for (int k = 0; k < 4; k++) {
      int e4 = tid + k*256, kk = e4 >> 5, c = (e4 & 31) << 2;
      cp16(Wd + kk*128 + c, d_W1t + (size_t)(Cin + kc + kk)*DoC + c);
    }
    #pragma unroll
    for (int k = 0; k < 2; k++) {
      int e4 = tid + k*256, kk = e4 >> 4, c = (e4 & 15) << 2;
      cp16(Xd + kk*64 + c, xb + (size_t)(kc + kk)*Np + n0 + c);
    }
  };
  load_chunk(0, 0); cp_commit();
  for (int ch = 0; ch < 8; ch++) {
    if (ch < 7) { load_chunk((ch+1)*32, (ch+1)&1); cp_commit(); cp_wait<1>(); }
    else        { cp_wait<0>(); }
    __syncthreads();
    const float* Wp = Ws + (ch & 1) * 4096;
    const float* Xp = Xs + (ch & 1) * 2048;
    #pragma unroll
    for (int kk = 0; kk < 32; kk++) {
      float a[8], bb[4];
      *(float4*)&a[0]  = *(const float4*)(Wp + kk*128 + ty*8);
      *(float4*)&a[4]  = *(const float4*)(Wp + kk*128 + ty*8 + 4);
      *(float4*)&bb[0] = *(const float4*)(Xp + kk*64 + tx*4);
      #pragma unroll
      for (int i = 0; i < 8; i++)
        #pragma unroll
        for (int j = 0; j < 4; j++) acc[i][j] = fmaf(a[i], bb[j], acc[i][j]);
    }
    __syncthreads();
  }
  #pragma unroll
  for (int j = 0; j < 4; j++) {
    float* dst = &d_P[(((size_t)b * Np) + n0 + tx*4 + j) * DoC + ty*8];
    *(float4*)dst       = make_float4(acc[0][j], acc[1][j], acc[2][j], acc[3][j]);
    *(float4*)(dst + 4) = make_float4(acc[4][j], acc[5][j], acc[6][j], acc[7][j]);
  }
}

// ---------------- z1 = W1a @ x + gather(P) [merge inlined], + shfl stats ----------------
__global__ __launch_bounds__(256, 2) void gemm1_kernel(
    const float* __restrict__ x, const float* __restrict__ xyz) {
  extern __shared__ float smem[];
  float* Ws   = smem;                    // [2][32][128]
  float* Xs   = smem + 8192;             // [2][32][128]
  int*   sidx = (int*)(smem + 16384);    // 384
  float* sw   = smem + 16768;            // 384
  int n0g = blockIdx.x << 7;
  int b   = n0g >> 14;
  int m0  = n0g & (Mq - 1);
  int tid = threadIdx.x;
  int tx = tid & 15, ty = tid >> 4;
  const float* xb = x + (size_t)b * Cin * Mq;
  float acc[8][8];
  #pragma unroll
  for (int i = 0; i < 8; i++)
    #pragma unroll
    for (int j = 0; j < 8; j++) acc[i][j] = 0.0f;

  auto load_chunk = [&](int kc, int s) {
    float* Wd = Ws + s * 4096;
    float* Xd = Xs + s * 4096;
    #pragma unroll
    for (int k = 0; k < 4; k++) {
      int e4 = tid + k*256, kk = e4 >> 5, c = (e4 & 31) << 2;
      cp16(Wd + kk*128 + c, d_W1t + (size_t)(kc + kk)*DoC + c);
      cp16(Xd + kk*128 + c, xb + (size_t)(kc + kk)*Mq + m0 + c);
    }
  };
  load_chunk(0, 0); cp_commit();

  // inline 6-candidate merge for this block's 128 queries (threads 0..127)
  if (tid < 128) {
    int m = m0 + tid;
    const float* qp = xyz + (size_t)b * 3 * Mq;
    float qx = qp[m], qy = qp[Mq + m], qz = qp[2*Mq + m];
    float qq = fmaf(qx, qx, fmaf(qy, qy, qz*qz));
    float c0 = 3.4e38f, c1 = 3.4e38f, c2 = 3.4e38f;
    int j0 = 0, j1 = 0, j2 = 0;
    size_t base = (size_t)(b * Mq + m) * 6;
    #pragma unroll
    for (int t = 0; t < 6; t++) {          // half0 first -> stable on ties
      float e = d_cd[base + t];
      int  id = d_ci[base + t];
      if (e < c2) {
        if (e < c1) {
          c2 = c1; j2 = j1;
          if (e < c0) { c1 = c0; j1 = j0; c0 = e; j0 = id; }
          else        { c1 = e; j1 = id; }
        } else { c2 = e; j2 = id; }
      }
    }
    float d0  = fmaxf(c0 + qq, 0.0f);
    float d1  = fmaxf(c1 + qq, 0.0f);
    float d2v = fmaxf(c2 + qq, 0.0f);
    float w0 = 1.0f / (d0 + 1e-8f);
    float w1 = 1.0f / (d1 + 1e-8f);
    float w2 = 1.0f / (d2v + 1e-8f);
    float inv = 1.0f / (w0 + w1 + w2);
    sidx[tid*3 + 0] = j0; sidx[tid*3 + 1] = j1; sidx[tid*3 + 2] = j2;
    sw  [tid*3 + 0] = w0*inv; sw[tid*3 + 1] = w1*inv; sw[tid*3 + 2] = w2*inv;
  }

  for (int ch = 0; ch < 4; ch++) {
    if (ch < 3) { load_chunk((ch+1)*32, (ch+1)&1); cp_commit(); cp_wait<1>(); }
    else        { cp_wait<0>(); }
    __syncthreads();
    const float* Wp = Ws + (ch & 1) * 4096;
    const float* Xp = Xs + (ch & 1) * 4096;
    #pragma unroll
    for (int kk = 0; kk < 32; kk++) {
      float a[8], bb[8];
      *(float4*)&a[0]  = *(const float4*)(Wp + kk*128 + ty*8);
      *(float4*)&a[4]  = *(const float4*)(Wp + kk*128 + ty*8 + 4);
      *(float4*)&bb[0] = *(const float4*)(Xp + kk*128 + tx*8);
      *(float4*)&bb[4] = *(const float4*)(Xp + kk*128 + tx*8 + 4);
      #pragma unroll
      for (int i = 0; i < 8; i++)
        #pragma unroll
        for (int j = 0; j < 8; j++) acc[i][j] = fmaf(a[i], bb[j], acc[i][j]);
    }
    __syncthreads();
  }

  // gather-interpolate through P
  #pragma unroll
  for (int j = 0; j < 8; j++) {
    int col = tx*8 + j;
    #pragma unroll
    for (int t = 0; t < 3; t++) {
      int   id = sidx[col*3 + t];
      float wt = sw  [col*3 + t];
      const float* pr = &d_P[(((size_t)b * Np) + id) * DoC + ty*8];
      float4 p0 = *(const float4*)pr;
      float4 p1 = *(const float4*)(pr + 4);
      acc[0][j] = fmaf(wt, p0.x, acc[0][j]);
      acc[1][j] = fmaf(wt, p0.y, acc[1][j]);
      acc[2][j] = fmaf(wt, p0.z, acc[2][j]);
      acc[3][j] = fmaf(wt, p0.w, acc[3][j]);
      acc[4][j] = fmaf(wt, p1.x, acc[4][j]);
      acc[5][j] = fmaf(wt, p1.y, acc[5][j]);
      acc[6][j] = fmaf(wt, p1.z, acc[6][j]);
      acc[7][j] = fmaf(wt, p1.w, acc[7][j]);
    }
  }

  // store z1
  #pragma unroll
  for (int i = 0; i < 8; i++) {
    float* dst = &d_z1[((size_t)(b * DoC + ty*8 + i)) * Mq + m0 + tx*8];
    *(float4*)dst       = make_float4(acc[i][0], acc[i][1], acc[i][2], acc[i][3]);
    *(float4*)(dst + 4) = make_float4(acc[i][4], acc[i][5], acc[i][6], acc[i][7]);
  }

  // shfl-butterfly stats over the 16 tx lanes
  float s8[8], q8[8];
  #pragma unroll
  for (int i = 0; i < 8; i++) {
    float s = 0.0f, q = 0.0f;
    #pragma unroll
    for (int j = 0; j < 8; j++) { s += acc[i][j]; q += acc[i][j]*acc[i][j]; }
    s8[i] = s; q8[i] = q;
  }
  #pragma unroll
  for (int off = 8; off >= 1; off >>= 1) {
    #pragma unroll
    for (int i = 0; i < 8; i++) {
      s8[i] += __shfl_xor_sync(0xffffffffu, s8[i], off);
      q8[i] += __shfl_xor_sync(0xffffffffu, q8[i], off);
    }
  }
  if (tx == 0) {
    #pragma unroll
    for (int i = 0; i < 8; i++) {
      d_psum[(ty*8 + i) * NBLK + blockIdx.x] = s8[i];
      d_psq [(ty*8 + i) * NBLK + blockIdx.x] = q8[i];
    }
  }
}

// ---------------- BN1 finalize: one block per channel, coalesced ----------------
__global__ __launch_bounds__(256) void bn_finalize_kernel(
    const float* __restrict__ g, const float* __restrict__ bias) {
  __shared__ float ss[256], sq[256];
  int ch = blockIdx.x;       // 128 blocks
  int tid = threadIdx.x;     // 256 = NBLK
  ss[tid] = d_psum[ch * NBLK + tid];
  sq[tid] = d_psq [ch * NBLK + tid];
  __syncthreads();
  #pragma unroll
  for (int off = 128; off >= 1; off >>= 1) {
    if (tid < off) { ss[tid] += ss[tid + off]; sq[tid] += sq[tid + off]; }
    __syncthreads();
  }
  if (tid == 0) {
    const float invN = 1.0f / (float)NCOLS;
    float mean = ss[0] * invN;
    float var  = sq[0] * invN - mean * mean;
    float rstd = rsqrtf(var + 1e-5f);
    float a = g[ch] * rstd;
    float d = bias[ch] - mean * a;
    d_bn1[ch] = a; d_bn1[DoC + ch] = d;
  }
}

// ---------------- z2 = W2 @ relu(bn1(z1)), + shfl stats ----------------
__global__ __launch_bounds__(256, 2) void gemm2_kernel() {
  extern __shared__ float smem[];
  float* Ws  = smem;             // [2][32][128]
  float* Xs  = smem + 8192;      // [2][32][128]
  float* sa  = smem + 16384;     // 128
  float* sd  = smem + 16512;     // 128
  int n0g = blockIdx.x << 7;
  int b   = n0g >> 14;
  int m0  = n0g & (Mq - 1);
  int tid = threadIdx.x;
  int tx = tid & 15, ty = tid >> 4;
  if (tid < 128) { sa[tid] = d_bn1[tid]; sd[tid] = d_bn1[DoC + tid]; }
  const float* zb = d_z1 + (size_t)b * DoC * Mq;
  float acc[8][8];
  #pragma unroll
  for (int i = 0; i < 8; i++)
    #pragma unroll
    for (int j = 0; j < 8; j++) acc[i][j] = 0.0f;

  auto load_chunk = [&](int kc, int s) {
    float* Wd = Ws + s * 4096;
    float* Xd = Xs + s * 4096;
    #pragma unroll
    for (int k = 0; k < 4; k++) {
      int e4 = tid + k*256, kk = e4 >> 5, c = (e4 & 31) << 2;
      cp16(Wd + kk*128 + c, d_W2t + (size_t)(kc + kk)*DoC + c);
      cp16(Xd + kk*128 + c, zb + (size_t)(kc + kk)*Mq + m0 + c);
    }
  };
  load_chunk(0, 0); cp_commit();
  for (int ch = 0; ch < 4; ch++) {
    if (ch < 3) { load_chunk((ch+1)*32, (ch+1)&1); cp_commit(); cp_wait<1>(); }
    else        { cp_wait<0>(); }
    __syncthreads();
    float* Xp = Xs + (ch & 1) * 4096;
    const float* Wp = Ws + (ch & 1) * 4096;
    int kc = ch * 32;
    // apply relu(bn1(.)) in place on this chunk
    #pragma unroll
    for (int k = 0; k < 4; k++) {
      int e4 = tid + k*256, kk = e4 >> 5, c = (e4 & 31) << 2;
      float A = sa[kc + kk], D = sd[kc + kk];
      float4 v = *(float4*)(Xp + kk*128 + c);
      v.x = fmaxf(fmaf(A, v.x, D), 0.0f);
      v.y = fmaxf(fmaf(A, v.y, D), 0.0f);
      v.z = fmaxf(fmaf(A, v.z, D), 0.0f);
      v.w = fmaxf(fmaf(A, v.w, D), 0.0f);
      *(float4*)(Xp + kk*128 + c) = v;
    }
    __syncthreads();
    #pragma unroll
    for (int kk = 0; kk < 32; kk++) {
      float a[8], bb[8];
      *(float4*)&a[0]  = *(const float4*)(Wp + kk*128 + ty*8);
      *(float4*)&a[4]  = *(const float4*)(Wp + kk*128 + ty*8 + 4);
      *(float4*)&bb[0] = *(const float4*)(Xp + kk*128 + tx*8);
      *(float4*)&bb[4] = *(const float4*)(Xp + kk*128 + tx*8 + 4);
      #pragma unroll
      for (int i = 0; i < 8; i++)
        #pragma unroll
        for (int j = 0; j < 8; j++) acc[i][j] = fmaf(a[i], bb[j], acc[i][j]);
    }
    __syncthreads();
  }

  #pragma unroll
  for (int i = 0; i < 8; i++) {
    float* dst = &d_z2[((size_t)(b * DoC + ty*8 + i)) * Mq + m0 + tx*8];
    *(float4*)dst       = make_float4(acc[i][0], acc[i][1], acc[i][2], acc[i][3]);
    *(float4*)(dst + 4) = make_float4(acc[i][4], acc[i][5], acc[i][6], acc[i][7]);
  }

  float s8[8], q8[8];
  #pragma unroll
  for (int i = 0; i < 8; i++) {
    float s = 0.0f, q = 0.0f;
    #pragma unroll
    for (int j = 0; j < 8; j++) { s += acc[i][j]; q += acc[i][j]*acc[i][j]; }
    s8[i] = s; q8[i] = q;
  }
  #pragma unroll
  for (int off = 8; off >= 1; off >>= 1) {
    #pragma unroll
    for (int i = 0; i < 8; i++) {
      s8[i] += __shfl_xor_sync(0xffffffffu, s8[i], off);
      q8[i] += __shfl_xor_sync(0xffffffffu, q8[i], off);
    }
  }
  if (tx == 0) {
    #pragma unroll
    for (int i = 0; i < 8; i++) {
      d_psum[(ty*8 + i) * NBLK + blockIdx.x] = s8[i];
      d_psq [(ty*8 + i) * NBLK + blockIdx.x] = q8[i];
    }
  }
}

// ---------------- fused bn2-finalize + out = relu(bn2(z2)); one block/channel ----------------
__global__ __launch_bounds__(256) void final_kernel(
    const float* __restrict__ g, const float* __restrict__ bias,
    float* __restrict__ out) {
  __shared__ float ss[256], sq[256];
  __shared__ float sab[2];
  int ch = blockIdx.x;       // 128 blocks
  int tid = threadIdx.x;     // 256 = NBLK
  ss[tid] = d_psum[ch * NBLK + tid];
  sq[tid] = d_psq [ch * NBLK + tid];
  __syncthreads();
  #pragma unroll
  for (int off = 128; off >= 1; off >>= 1) {
    if (tid < off) { ss[tid] += ss[tid + off]; sq[tid] += sq[tid + off]; }
    __syncthreads();
  }
  if (tid == 0) {
    const float invN = 1.0f / (float)NCOLS;
    float mean = ss[0] * invN;
    float var  = sq[0] * invN - mean * mean;
    float rstd = rsqrtf(var + 1e-5f);
    float a = g[ch] * rstd;
    sab[0] = a;
    sab[1] = bias[ch] - mean * a;
  }
  __syncthreads();
  float a = sab[0], d = sab[1];
  #pragma unroll
  for (int b = 0; b < Bc; b++) {
    const float4* src = (const float4*)(d_z2 + ((size_t)(b * DoC + ch)) * Mq);
    float4*       dst = (float4*)(out + ((size_t)(b * DoC + ch)) * Mq);
    #pragma unroll 4
    for (int i = tid; i < Mq/4; i += 256) {
      float4 v = src[i];
      v.x = fmaxf(fmaf(a, v.x, d), 0.0f);
      v.y = fmaxf(fmaf(a, v.y, d), 0.0f);
      v.z = fmaxf(fmaf(a, v.z, d), 0.0f);
      v.w = fmaxf(fmaf(a, v.w, d), 0.0f);
      dst[i] = v;
    }
  }
}

// ---------------- launch ----------------
extern "C" void kernel_launch(void* const* d_in, const int* in_sizes, int n_in,
                              void* d_out, int out_size) {
  const float* x       = (const float*)d_in[0];
  const float* xyz     = (const float*)d_in[1];
  const float* sub_x   = (const float*)d_in[2];
  const float* sub_xyz = (const float*)d_in[3];
  const float* W1      = (const float*)d_in[4];
  const float* g1      = (const float*)d_in[5];
  const float* b1      = (const float*)d_in[6];
  const float* W2      = (const float*)d_in[7];
  const float* g2      = (const float*)d_in[8];
  const float* b2      = (const float*)d_in[9];
  float* out = (float*)d_out;

  const int smemF = 49152;
  const int smem1 = (16384 + 768) * 4;
  const int smem2 = (16384 + 256) * 4;
  cudaFuncSetAttribute(knn_gemmP_kernel, cudaFuncAttributeMaxDynamicSharedMemorySize, smemF);
  cudaFuncSetAttribute(gemm1_kernel, cudaFuncAttributeMaxDynamicSharedMemorySize, smem1);
  cudaFuncSetAttribute(gemm2_kernel, cudaFuncAttributeMaxDynamicSharedMemorySize, smem2);

  transpose_w_kernel<<<256, 256>>>(W1, W2);
  knn_gemmP_kernel<<<256, 256, smemF>>>(xyz, sub_xyz, sub_x);
  gemm1_kernel<<<256, 256, smem1>>>(x, xyz);
  bn_finalize_kernel<<<128, 256>>>(g1, b1);
  gemm2_kernel<<<256, 256, smem2>>>();
  final_kernel<<<128, 256>>>(g2, b2, out);
}

// round 13
// speedup vs baseline: 1.2414x; 1.2414x over previous
#include <cuda_runtime.h>

#define Bc   2
#define Mq   16384
#define Np   4096
#define Cin  128
#define CsF  256
#define DoC  128
#define NCOLS (Bc*Mq)        // 32768
#define NBLK  256            // gemm1/gemm2 grid
#define PH   2048            // points per half (knn split)

// ---------------- scratch (device globals; no runtime allocation) -------------
__device__ __align__(16) float d_W1t[384*DoC];
__device__ __align__(16) float d_W2t[DoC*DoC];
__device__ __align__(16) float d_P  [Bc*Np*DoC];
__device__ float d_cd[Bc*Mq*6];
__device__ int   d_ci[Bc*Mq*6];
__device__ __align__(16) float d_z1 [Bc*DoC*Mq];
__device__ __align__(16) float d_z2 [Bc*DoC*Mq];
__device__ __align__(16) float d_psum[DoC*NBLK];   // channel-major [ch][blk]
__device__ __align__(16) float d_psq [DoC*NBLK];
__device__ float d_bn1[2*DoC];

// ---------------- cp.async helpers ----------------
__device__ __forceinline__ void cp16(float* s, const float* g) {
  unsigned sa = (unsigned)__cvta_generic_to_shared(s);
  asm volatile("cp.async.cg.shared.global [%0], [%1], 16;\n" :: "r"(sa), "l"(g));
}
__device__ __forceinline__ void cp_commit() { asm volatile("cp.async.commit_group;\n"); }
template<int N> __device__ __forceinline__ void cp_wait() {
  asm volatile("cp.async.wait_group %0;\n" :: "n"(N));
}

// ---------------- W transpose ----------------
__global__ __launch_bounds__(256) void transpose_w_kernel(
    const float* __restrict__ W1, const float* __restrict__ W2) {
  int e = blockIdx.x * 256 + threadIdx.x;
  if (e < 384*DoC) {
    int k = e >> 7, o = e & 127;
    d_W1t[e] = W1[o*384 + k];
  } else {
    int e2 = e - 384*DoC;
    int k = e2 >> 7, o = e2 & 127;
    d_W2t[e2] = W2[o*DoC + k];
  }
}

// ---------------- fused: knn (blocks 0..255) + gemmP (blocks 256..383) ----------------
__global__ __launch_bounds__(256) void knn_gemmP_kernel(
    const float* __restrict__ xyz, const float* __restrict__ sub_xyz,
    const float* __restrict__ sub_x) {
  extern __shared__ float smem[];
  int bx = blockIdx.x;
  int tid = threadIdx.x;

  if (bx < 256) {
    // ---------------- knn role ----------------
    float4* pts = (float4*)smem;   // 32KB
    int b    = bx >> 7;
    int half = (bx >> 6) & 1;
    int m    = ((bx & 63) << 8) + tid;
    const float* sp = sub_xyz + (size_t)b * 3 * Np + half * PH;
    for (int i = tid; i < PH; i += 256) {
      float px = sp[i], py = sp[Np + i], pz = sp[2*Np + i];
      pts[i] = make_float4(px, py, pz, fmaf(px, px, fmaf(py, py, pz*pz)));
    }
    __syncthreads();
    const float* qp = xyz + (size_t)b * 3 * Mq;
    float nx = -2.0f * qp[m], ny = -2.0f * qp[Mq + m], nz = -2.0f * qp[2*Mq + m];

    float c0 = 3.4e38f, c1 = 3.4e38f, c2 = 3.4e38f;
    int j0 = 0, j1 = 0, j2 = 0;
    #pragma unroll 8
    for (int i = 0; i < PH; i++) {
      float4 p = pts[i];
      float e = fmaf(nx, p.x, fmaf(ny, p.y, fmaf(nz, p.z, p.w)));
      if (e < c2) {
        if (e < c1) {
          c2 = c1; j2 = j1;
          if (e < c0) { c1 = c0; j1 = j0; c0 = e; j0 = i; }
          else        { c1 = e; j1 = i; }
        } else { c2 = e; j2 = i; }
      }
    }
    size_t base = ((size_t)(b * Mq + m) * 2 + half) * 3;
    int off = half * PH;
    d_cd[base + 0] = c0; d_cd[base + 1] = c1; d_cd[base + 2] = c2;
    d_ci[base + 0] = j0 + off; d_ci[base + 1] = j1 + off; d_ci[base + 2] = j2 + off;
    return;
  }

  // ---------------- gemmP role ----------------
  int bxp = bx - 256;                 // 0..127
  float* Ws = smem;                   // [2][32][128]
  float* Xs = smem + 8192;            // [2][32][64]
  int b  = bxp >> 6;
  int n0 = (bxp & 63) << 6;
  int tx = tid & 15, ty = tid >> 4;
  const float* xb = sub_x + (size_t)b * CsF * Np;
  float acc[8][4];
  #pragma unroll
  for (int i = 0; i < 8; i++)
    #pragma unroll
    for (int j = 0; j < 4; j++) acc[i][j] = 0.0f;

  auto load_chunk = [&](int kc, int s) {
    float* Wd = Ws + s * 4096;
    float* Xd = Xs + s * 2048;
    #pragma unroll
    for (int k = 0; k < 4; k++) {
      int e4 = tid + k*256, kk = e4 >> 5, c = (e4 & 31) << 2;
      cp16(Wd + kk*128 + c, d_W1t + (size_t)(Cin + kc + kk)*DoC + c);
    }
    #pragma unroll
    for (int k = 0; k < 2; k++) {
      int e4 = tid + k*256, kk = e4 >> 4, c = (e4 & 15) << 2;
      cp16(Xd + kk*64 + c, xb + (size_t)(kc + kk)*Np + n0 + c);
    }
  };
  load_chunk(0, 0); cp_commit();
  for (int ch = 0; ch < 8; ch++) {
    if (ch < 7) { load_chunk((ch+1)*32, (ch+1)&1); cp_commit(); cp_wait<1>(); }
    else        { cp_wait<0>(); }
    __syncthreads();
    const float* Wp = Ws + (ch & 1) * 4096;
    const float* Xp = Xs + (ch & 1) * 2048;
    #pragma unroll
    for (int kk = 0; kk < 32; kk++) {
      float a[8], bb[4];
      *(float4*)&a[0]  = *(const float4*)(Wp + kk*128 + ty*8);
      *(float4*)&a[4]  = *(const float4*)(Wp + kk*128 + ty*8 + 4);
      *(float4*)&bb[0] = *(const float4*)(Xp + kk*64 + tx*4);
      #pragma unroll
      for (int i = 0; i < 8; i++)
        #pragma unroll
        for (int j = 0; j < 4; j++) acc[i][j] = fmaf(a[i], bb[j], acc[i][j]);
    }
    __syncthreads();
  }
  #pragma unroll
  for (int j = 0; j < 4; j++) {
    float* dst = &d_P[(((size_t)b * Np) + n0 + tx*4 + j) * DoC + ty*8];
    *(float4*)dst       = make_float4(acc[0][j], acc[1][j], acc[2][j], acc[3][j]);
    *(float4*)(dst + 4) = make_float4(acc[4][j], acc[5][j], acc[6][j], acc[7][j]);
  }
}

// ---------------- z1 = W1a @ x + gather(P) [merge inlined], + shfl stats ----------------
__global__ __launch_bounds__(256, 2) void gemm1_kernel(
    const float* __restrict__ x, const float* __restrict__ xyz) {
  extern __shared__ float smem[];
  float* Ws   = smem;                    // [2][32][128]
  float* Xs   = smem + 8192;             // [2][32][128]
  int*   sidx = (int*)(smem + 16384);    // 384
  float* sw   = smem + 16768;            // 384
  int n0g = blockIdx.x << 7;
  int b   = n0g >> 14;
  int m0  = n0g & (Mq - 1);
  int tid = threadIdx.x;
  int tx = tid & 15, ty = tid >> 4;
  const float* xb = x + (size_t)b * Cin * Mq;
  float acc[8][8];
  #pragma unroll
  for (int i = 0; i < 8; i++)
    #pragma unroll
    for (int j = 0; j < 8; j++) acc[i][j] = 0.0f;

  auto load_chunk = [&](int kc, int s) {
    float* Wd = Ws + s * 4096;
    float* Xd = Xs + s * 4096;
    #pragma unroll
    for (int k = 0; k < 4; k++) {
      int e4 = tid + k*256, kk = e4 >> 5, c = (e4 & 31) << 2;
      cp16(Wd + kk*128 + c, d_W1t + (size_t)(kc + kk)*DoC + c);
      cp16(Xd + kk*128 + c, xb + (size_t)(kc + kk)*Mq + m0 + c);
    }
  };
  load_chunk(0, 0); cp_commit();

  // inline 6-candidate merge for this block's 128 queries (threads 0..127)
  if (tid < 128) {
    int m = m0 + tid;
    const float* qp = xyz + (size_t)b * 3 * Mq;
    float qx = qp[m], qy = qp[Mq + m], qz = qp[2*Mq + m];
    float qq = fmaf(qx, qx, fmaf(qy, qy, qz*qz));
    float c0 = 3.4e38f, c1 = 3.4e38f, c2 = 3.4e38f;
    int j0 = 0, j1 = 0, j2 = 0;
    size_t base = (size_t)(b * Mq + m) * 6;
    #pragma unroll
    for (int t = 0; t < 6; t++) {          // half0 first -> stable on ties
      float e = d_cd[base + t];
      int  id = d_ci[base + t];
      if (e < c2) {
        if (e < c1) {
          c2 = c1; j2 = j1;
          if (e < c0) { c1 = c0; j1 = j0; c0 = e; j0 = id; }
          else        { c1 = e; j1 = id; }
        } else { c2 = e; j2 = id; }
      }
    }
    float d0  = fmaxf(c0 + qq, 0.0f);
    float d1  = fmaxf(c1 + qq, 0.0f);
    float d2v = fmaxf(c2 + qq, 0.0f);
    float w0 = 1.0f / (d0 + 1e-8f);
    float w1 = 1.0f / (d1 + 1e-8f);
    float w2 = 1.0f / (d2v + 1e-8f);
    float inv = 1.0f / (w0 + w1 + w2);
    sidx[tid*3 + 0] = j0; sidx[tid*3 + 1] = j1; sidx[tid*3 + 2] = j2;
    sw  [tid*3 + 0] = w0*inv; sw[tid*3 + 1] = w1*inv; sw[tid*3 + 2] = w2*inv;
  }

  for (int ch = 0; ch < 4; ch++) {
    if (ch < 3) { load_chunk((ch+1)*32, (ch+1)&1); cp_commit(); cp_wait<1>(); }
    else        { cp_wait<0>(); }
    __syncthreads();
    const float* Wp = Ws + (ch & 1) * 4096;
    const float* Xp = Xs + (ch & 1) * 4096;
    #pragma unroll
    for (int kk = 0; kk < 32; kk++) {
      float a[8], bb[8];
      *(float4*)&a[0]  = *(const float4*)(Wp + kk*128 + ty*8);
      *(float4*)&a[4]  = *(const float4*)(Wp + kk*128 + ty*8 + 4);
      *(float4*)&bb[0] = *(const float4*)(Xp + kk*128 + tx*8);
      *(float4*)&bb[4] = *(const float4*)(Xp + kk*128 + tx*8 + 4);
      #pragma unroll
      for (int i = 0; i < 8; i++)
        #pragma unroll
        for (int j = 0; j < 8; j++) acc[i][j] = fmaf(a[i], bb[j], acc[i][j]);
    }
    __syncthreads();
  }

  // gather-interpolate through P
  #pragma unroll
  for (int j = 0; j < 8; j++) {
    int col = tx*8 + j;
    #pragma unroll
    for (int t = 0; t < 3; t++) {
      int   id = sidx[col*3 + t];
      float wt = sw  [col*3 + t];
      const float* pr = &d_P[(((size_t)b * Np) + id) * DoC + ty*8];
      float4 p0 = *(const float4*)pr;
      float4 p1 = *(const float4*)(pr + 4);
      acc[0][j] = fmaf(wt, p0.x, acc[0][j]);
      acc[1][j] = fmaf(wt, p0.y, acc[1][j]);
      acc[2][j] = fmaf(wt, p0.z, acc[2][j]);
      acc[3][j] = fmaf(wt, p0.w, acc[3][j]);
      acc[4][j] = fmaf(wt, p1.x, acc[4][j]);
      acc[5][j] = fmaf(wt, p1.y, acc[5][j]);
      acc[6][j] = fmaf(wt, p1.z, acc[6][j]);
      acc[7][j] = fmaf(wt, p1.w, acc[7][j]);
    }
  }

  // store z1
  #pragma unroll
  for (int i = 0; i < 8; i++) {
    float* dst = &d_z1[((size_t)(b * DoC + ty*8 + i)) * Mq + m0 + tx*8];
    *(float4*)dst       = make_float4(acc[i][0], acc[i][1], acc[i][2], acc[i][3]);
    *(float4*)(dst + 4) = make_float4(acc[i][4], acc[i][5], acc[i][6], acc[i][7]);
  }

  // shfl-butterfly stats over the 16 tx lanes
  float s8[8], q8[8];
  #pragma unroll
  for (int i = 0; i < 8; i++) {
    float s = 0.0f, q = 0.0f;
    #pragma unroll
    for (int j = 0; j < 8; j++) { s += acc[i][j]; q += acc[i][j]*acc[i][j]; }
    s8[i] = s; q8[i] = q;
  }
  #pragma unroll
  for (int off = 8; off >= 1; off >>= 1) {
    #pragma unroll
    for (int i = 0; i < 8; i++) {
      s8[i] += __shfl_xor_sync(0xffffffffu, s8[i], off);
      q8[i] += __shfl_xor_sync(0xffffffffu, q8[i], off);
    }
  }
  if (tx == 0) {
    #pragma unroll
    for (int i = 0; i < 8; i++) {
      d_psum[(ty*8 + i) * NBLK + blockIdx.x] = s8[i];
      d_psq [(ty*8 + i) * NBLK + blockIdx.x] = q8[i];
    }
  }
}

// ---------------- BN1 finalize: one block per channel, coalesced ----------------
__global__ __launch_bounds__(256) void bn_finalize_kernel(
    const float* __restrict__ g, const float* __restrict__ bias) {
  __shared__ float ss[256], sq[256];
  int ch = blockIdx.x;       // 128 blocks
  int tid = threadIdx.x;     // 256 = NBLK
  ss[tid] = d_psum[ch * NBLK + tid];
  sq[tid] = d_psq [ch * NBLK + tid];
  __syncthreads();
  #pragma unroll
  for (int off = 128; off >= 1; off >>= 1) {
    if (tid < off) { ss[tid] += ss[tid + off]; sq[tid] += sq[tid + off]; }
    __syncthreads();
  }
  if (tid == 0) {
    const float invN = 1.0f / (float)NCOLS;
    float mean = ss[0] * invN;
    float var  = sq[0] * invN - mean * mean;
    float rstd = rsqrtf(var + 1e-5f);
    float a = g[ch] * rstd;
    float d = bias[ch] - mean * a;
    d_bn1[ch] = a; d_bn1[DoC + ch] = d;
  }
}

// ---------------- z2 = W2 @ relu(bn1(z1)), + shfl stats ----------------
__global__ __launch_bounds__(256, 2) void gemm2_kernel() {
  extern __shared__ float smem[];
  float* Ws  = smem;             // [2][32][128]
  float* Xs  = smem + 8192;      // [2][32][128]
  float* sa  = smem + 16384;     // 128
  float* sd  = smem + 16512;     // 128
  int n0g = blockIdx.x << 7;
  int b   = n0g >> 14;
  int m0  = n0g & (Mq - 1);
  int tid = threadIdx.x;
  int tx = tid & 15, ty = tid >> 4;
  if (tid < 128) { sa[tid] = d_bn1[tid]; sd[tid] = d_bn1[DoC + tid]; }
  const float* zb = d_z1 + (size_t)b * DoC * Mq;
  float acc[8][8];
  #pragma unroll
  for (int i = 0; i < 8; i++)
    #pragma unroll
    for (int j = 0; j < 8; j++) acc[i][j] = 0.0f;

  auto load_chunk = [&](int kc, int s) {
    float* Wd = Ws + s * 4096;
    float* Xd = Xs + s * 4096;
    #pragma unroll
    for (int k = 0; k < 4; k++) {
      int e4 = tid + k*256, kk = e4 >> 5, c = (e4 & 31) << 2;
      cp16(Wd + kk*128 + c, d_W2t + (size_t)(kc + kk)*DoC + c);
      cp16(Xd + kk*128 + c, zb + (size_t)(kc + kk)*Mq + m0 + c);
    }
  };
  load_chunk(0, 0); cp_commit();
  for (int ch = 0; ch < 4; ch++) {
    if (ch < 3) { load_chunk((ch+1)*32, (ch+1)&1); cp_commit(); cp_wait<1>(); }
    else        { cp_wait<0>(); }
    __syncthreads();
    float* Xp = Xs + (ch & 1) * 4096;
    const float* Wp = Ws + (ch & 1) * 4096;
    int kc = ch * 32;
    // apply relu(bn1(.)) in place on this chunk
    #pragma unroll
    for (int k = 0; k < 4; k++) {
      int e4 = tid + k*256, kk = e4 >> 5, c = (e4 & 31) << 2;
      float A = sa[kc + kk], D = sd[kc + kk];
      float4 v = *(float4*)(Xp + kk*128 + c);
      v.x = fmaxf(fmaf(A, v.x, D), 0.0f);
      v.y = fmaxf(fmaf(A, v.y, D), 0.0f);
      v.z = fmaxf(fmaf(A, v.z, D), 0.0f);
      v.w = fmaxf(fmaf(A, v.w, D), 0.0f);
      *(float4*)(Xp + kk*128 + c) = v;
    }
    __syncthreads();
    #pragma unroll
    for (int kk = 0; kk < 32; kk++) {
      float a[8], bb[8];
      *(float4*)&a[0]  = *(const float4*)(Wp + kk*128 + ty*8);
      *(float4*)&a[4]  = *(const float4*)(Wp + kk*128 + ty*8 + 4);
      *(float4*)&bb[0] = *(const float4*)(Xp + kk*128 + tx*8);
      *(float4*)&bb[4] = *(const float4*)(Xp + kk*128 + tx*8 + 4);
      #pragma unroll
      for (int i = 0; i < 8; i++)
        #pragma unroll
        for (int j = 0; j < 8; j++) acc[i][j] = fmaf(a[i], bb[j], acc[i][j]);
    }
    __syncthreads();
  }

  #pragma unroll
  for (int i = 0; i < 8; i++) {
    float* dst = &d_z2[((size_t)(b * DoC + ty*8 + i)) * Mq + m0 + tx*8];
    *(float4*)dst       = make_float4(acc[i][0], acc[i][1], acc[i][2], acc[i][3]);
    *(float4*)(dst + 4) = make_float4(acc[i][4], acc[i][5], acc[i][6], acc[i][7]);
  }

  float s8[8], q8[8];
  #pragma unroll
  for (int i = 0; i < 8; i++) {
    float s = 0.0f, q = 0.0f;
    #pragma unroll
    for (int j = 0; j < 8; j++) { s += acc[i][j]; q += acc[i][j]*acc[i][j]; }
    s8[i] = s; q8[i] = q;
  }
  #pragma unroll
  for (int off = 8; off >= 1; off >>= 1) {
    #pragma unroll
    for (int i = 0; i < 8; i++) {
      s8[i] += __shfl_xor_sync(0xffffffffu, s8[i], off);
      q8[i] += __shfl_xor_sync(0xffffffffu, q8[i], off);
    }
  }
  if (tx == 0) {
    #pragma unroll
    for (int i = 0; i < 8; i++) {
      d_psum[(ty*8 + i) * NBLK + blockIdx.x] = s8[i];
      d_psq [(ty*8 + i) * NBLK + blockIdx.x] = q8[i];
    }
  }
}

// ---------------- fused bn2-finalize + out = relu(bn2(z2)); 8 slices/channel ----------------
__global__ __launch_bounds__(256) void final_kernel(
    const float* __restrict__ g, const float* __restrict__ bias,
    float* __restrict__ out) {
  __shared__ float ss[256], sq[256];
  __shared__ float sab[2];
  int bx = blockIdx.x;           // 1024 blocks
  int ch = bx >> 3, sl = bx & 7; // channel, slice
  int tid = threadIdx.x;         // 256 = NBLK
  // redundant per-slice reduction: identical order in all 8 blocks of a channel
  ss[tid] = d_psum[ch * NBLK + tid];
  sq[tid] = d_psq [ch * NBLK + tid];
  __syncthreads();
  #pragma unroll
  for (int off = 128; off >= 1; off >>= 1) {
    if (tid < off) { ss[tid] += ss[tid + off]; sq[tid] += sq[tid + off]; }
    __syncthreads();
  }
  if (tid == 0) {
    const float invN = 1.0f / (float)NCOLS;
    float mean = ss[0] * invN;
    float var  = sq[0] * invN - mean * mean;
    float rstd = rsqrtf(var + 1e-5f);
    float a = g[ch] * rstd;
    sab[0] = a;
    sab[1] = bias[ch] - mean * a;
  }
  __syncthreads();
  float a = sab[0], d = sab[1];
  int c0 = sl * (Mq/8);          // 2048-column slice
  #pragma unroll
  for (int b = 0; b < Bc; b++) {
    const float4* src = (const float4*)(d_z2 + ((size_t)(b * DoC + ch)) * Mq + c0);
    float4*       dst = (float4*)(out + ((size_t)(b * DoC + ch)) * Mq + c0);
    #pragma unroll
    for (int i = tid; i < (Mq/8)/4; i += 256) {   // 512 float4s, 2 iters/thread
      float4 v = src[i];
      v.x = fmaxf(fmaf(a, v.x, d), 0.0f);
      v.y = fmaxf(fmaf(a, v.y, d), 0.0f);
      v.z = fmaxf(fmaf(a, v.z, d), 0.0f);
      v.w = fmaxf(fmaf(a, v.w, d), 0.0f);
      dst[i] = v;
    }
  }
}

// ---------------- launch ----------------
extern "C" void kernel_launch(void* const* d_in, const int* in_sizes, int n_in,
                              void* d_out, int out_size) {
  const float* x       = (const float*)d_in[0];
  const float* xyz     = (const float*)d_in[1];
  const float* sub_x   = (const float*)d_in[2];
  const float* sub_xyz = (const float*)d_in[3];
  const float* W1      = (const float*)d_in[4];
  const float* g1      = (const float*)d_in[5];
  const float* b1      = (const float*)d_in[6];
  const float* W2      = (const float*)d_in[7];
  const float* g2      = (const float*)d_in[8];
  const float* b2      = (const float*)d_in[9];
  float* out = (float*)d_out;

  const int smemF = 49152;
  const int smem1 = (16384 + 768) * 4;
  const int smem2 = (16384 + 256) * 4;
  cudaFuncSetAttribute(knn_gemmP_kernel, cudaFuncAttributeMaxDynamicSharedMemorySize, smemF);
  cudaFuncSetAttribute(gemm1_kernel, cudaFuncAttributeMaxDynamicSharedMemorySize, smem1);
  cudaFuncSetAttribute(gemm2_kernel, cudaFuncAttributeMaxDynamicSharedMemorySize, smem2);

  transpose_w_kernel<<<256, 256>>>(W1, W2);
  knn_gemmP_kernel<<<384, 256, smemF>>>(xyz, sub_xyz, sub_x);
  gemm1_kernel<<<256, 256, smem1>>>(x, xyz);
  bn_finalize_kernel<<<128, 256>>>(g1, b1);
  gemm2_kernel<<<256, 256, smem2>>>();
  final_kernel<<<1024, 256>>>(g2, b2, out);
}